// round 7
// baseline (speedup 1.0000x reference)
#include <cuda_runtime.h>
#include <cstdint>

#define NSP     2048
#define BATCH   64
#define NSTEP   1000
#define KEX     32            // steps between ghost exchanges
#define GW      64            // ghost width per side (= 2 * KEX)
#define OWNW    256           // owned elems per compute warp
#define EPT     12            // elems per thread ((OWNW+2*GW)/32)
#define CWARPS  4             // compute warps
#define THREADS 256           // 4 compute + 4 writer warps
#define OWN_CTA 1024          // owned per CTA (half row)
#define NBUF    8             // staging ring depth (frames)

typedef unsigned long long u64;

__device__ __forceinline__ u64 pk(float lo, float hi) {
    u64 r; asm("mov.b64 %0,{%1,%2};" : "=l"(r) : "f"(lo), "f"(hi)); return r;
}
__device__ __forceinline__ void upk(u64 v, float& lo, float& hi) {
    asm("mov.b64 {%0,%1},%2;" : "=f"(lo), "=f"(hi) : "l"(v));
}
__device__ __forceinline__ u64 fma2(u64 a, u64 b, u64 c) {
    u64 d; asm("fma.rn.f32x2 %0,%1,%2,%3;" : "=l"(d) : "l"(a), "l"(b), "l"(c)); return d;
}
__device__ __forceinline__ u64 add2(u64 a, u64 b) {
    u64 d; asm("add.rn.f32x2 %0,%1,%2;" : "=l"(d) : "l"(a), "l"(b)); return d;
}
__device__ __forceinline__ u64 mul2(u64 a, u64 b) {
    u64 d; asm("mul.rn.f32x2 %0,%1,%2;" : "=l"(d) : "l"(a), "l"(b)); return d;
}

__global__ void __cluster_dims__(2, 1, 1) __launch_bounds__(THREADS, 1)
ks_kernel(const float* __restrict__ u0,
          const float* __restrict__ cp,
          const float* __restrict__ ap,
          const float* __restrict__ bp,
          float* __restrict__ out) {
    __shared__ alignas(16) float sh_ex[OWN_CTA];                 // exchange staging (4 KB)
    __shared__ alignas(16) float ring[CWARPS][NBUF][OWNW];       // store ring (32 KB)
    __shared__ unsigned int head[CWARPS];                        // produced-frame count
    __shared__ volatile unsigned int done[CWARPS];               // consumed-frame count

    const int row  = blockIdx.x >> 1;
    const int half = blockIdx.x & 1;
    const int w    = threadIdx.x >> 5;
    const int lane = threadIdx.x & 31;

    if (threadIdx.x < CWARPS) { head[threadIdx.x] = 0u; done[threadIdx.x] = 0u; }
    __syncthreads();

    const size_t FR = (size_t)BATCH * NSP;

    // initial cluster arrive — pairs with first exchange wait (or final wait)
    asm volatile("barrier.cluster.arrive.aligned;" ::: "memory");

    if (w < CWARPS) {
        // ================= COMPUTE WARP =================
        const float dt = 0.01f;
        const float Af = -0.5f * dt * (*cp);
        const float Bc = -dt * (*ap);
        const float Cc = -dt * (*bp);
        const float c0f = 1.0f - 2.0f * Bc + 6.0f * Cc;
        const float c1f = Bc - 4.0f * Cc;
        const u64 C0 = pk(c0f, c0f), C1 = pk(c1f, c1f), C2 = pk(Cc, Cc);
        const u64 AV = pk(Af, Af),   M1 = pk(-1.0f, -1.0f);

        const int base = half * OWN_CTA + w * OWNW - GW;   // may be negative
        const int j0   = lane * EPT;

        // ---- initial load: 3 float4 groups per thread, periodic wrap ----
        u64 P[6];
        const float* urow = u0 + (size_t)row * NSP;
        #pragma unroll
        for (int g = 0; g < 3; g++) {
            int pos = (base + j0 + 4 * g) & (NSP - 1);
            float4 v = *reinterpret_cast<const float4*>(urow + pos);
            P[2 * g]     = pk(v.x, v.y);
            P[2 * g + 1] = pk(v.z, v.w);
        }

        // ---- frame 0 = u0 (owned groups only; one-time direct store) ----
        {
            float* o0 = out + (size_t)row * NSP;
            #pragma unroll
            for (int g = 0; g < 3; g++) {
                int j = j0 + 4 * g;
                if (j >= GW && j < GW + OWNW) {
                    ulonglong2 v; v.x = P[2 * g]; v.y = P[2 * g + 1];
                    *reinterpret_cast<ulonglong2*>(o0 + base + j) = v;
                }
            }
        }

        const uint32_t shbase = (uint32_t)__cvta_generic_to_shared(sh_ex);
        const uint32_t ha     = (uint32_t)__cvta_generic_to_shared(&head[w]);
        const uint32_t peer   = (uint32_t)(half ^ 1);

        #pragma unroll 1
        for (int t = 0; t < NSTEP; t++) {
            if (t > 0 && (t & (KEX - 1)) == 0) {
                // ===== ghost exchange (every KEX steps) =====
                asm volatile("barrier.cluster.wait.aligned;" ::: "memory");

                #pragma unroll
                for (int g = 0; g < 3; g++) {
                    int j = j0 + 4 * g;
                    if (j >= GW && j < GW + OWNW) {
                        float a, b, c, d;
                        upk(P[2 * g], a, b); upk(P[2 * g + 1], c, d);
                        *reinterpret_cast<float4*>(&sh_ex[w * OWNW + (j - GW)]) =
                            make_float4(a, b, c, d);
                    }
                }
                asm volatile("bar.sync 1, 128;" ::: "memory");
                asm volatile("barrier.cluster.arrive.aligned;" ::: "memory");
                asm volatile("barrier.cluster.wait.aligned;"   ::: "memory");

                #pragma unroll
                for (int g = 0; g < 3; g++) {
                    int j = j0 + 4 * g;
                    if (j < GW || j >= GW + OWNW) {
                        int pos = (base + j) & (NSP - 1);
                        int h2  = pos >> 10;
                        int idx = pos & (OWN_CTA - 1);
                        float4 v;
                        if (h2 == half) {
                            v = *reinterpret_cast<const float4*>(&sh_ex[idx]);
                        } else {
                            uint32_t pa;
                            asm("mapa.shared::cluster.u32 %0, %1, %2;"
                                : "=r"(pa) : "r"(shbase + (uint32_t)idx * 4u), "r"(peer));
                            asm volatile("ld.shared::cluster.v4.f32 {%0,%1,%2,%3}, [%4];"
                                         : "=f"(v.x), "=f"(v.y), "=f"(v.z), "=f"(v.w)
                                         : "r"(pa));
                        }
                        P[2 * g]     = pk(v.x, v.y);
                        P[2 * g + 1] = pk(v.z, v.w);
                    }
                }
                asm volatile("bar.sync 1, 128;" ::: "memory");
                asm volatile("barrier.cluster.arrive.aligned;" ::: "memory");
            }

            // ---- ring credit: slot t%NBUF free when frame t-NBUF consumed ----
            while ((int)t - (int)done[w] >= NBUF) __nanosleep(32);

            // ===== one explicit-Euler step, fully in registers =====
            float e[16];
            #pragma unroll
            for (int p = 0; p < 6; p++) upk(P[p], e[2 + 2 * p], e[3 + 2 * p]);
            e[0]  = __shfl_up_sync(0xffffffffu, e[12], 1);
            e[1]  = __shfl_up_sync(0xffffffffu, e[13], 1);
            e[14] = __shfl_down_sync(0xffffffffu, e[2], 1);
            e[15] = __shfl_down_sync(0xffffffffu, e[3], 1);

            u64 A[8];
            A[0] = pk(e[0], e[1]);
            #pragma unroll
            for (int p = 0; p < 6; p++) A[p + 1] = P[p];
            A[7] = pk(e[14], e[15]);
            u64 O[7];
            #pragma unroll
            for (int i = 0; i < 7; i++) O[i] = pk(e[2 * i + 1], e[2 * i + 2]);

            u64 r[6];
            #pragma unroll
            for (int p = 0; p < 6; p++) {
                u64 u   = A[p + 1];
                u64 d1  = fma2(M1, O[p], O[p + 1]);     // up1 - um1
                u64 t1  = fma2(AV, d1, C0);             // c0 + A*d1
                u64 s1  = add2(O[p + 1], O[p]);
                u64 s2  = add2(A[p + 2], A[p]);
                u64 m   = mul2(C2, s2);
                m       = fma2(C1, s1, m);
                r[p]    = fma2(u, t1, m);               // u*(c0+A*d1) + (C1*s1+C2*s2)
            }

            // ---- stage owned groups into ring slot (conflict-free STS.128) ----
            {
                float* sb = &ring[w][t & (NBUF - 1)][0];
                #pragma unroll
                for (int g = 0; g < 3; g++) {
                    int j = j0 + 4 * g;
                    if (j >= GW && j < GW + OWNW) {
                        ulonglong2 v; v.x = r[2 * g]; v.y = r[2 * g + 1];
                        *reinterpret_cast<ulonglong2*>(sb + (j - GW)) = v;
                    }
                }
            }
            #pragma unroll
            for (int p = 0; p < 6; p++) P[p] = r[p];

            // ---- publish pair of frames every 2 steps ----
            if (t & 1) {
                __syncwarp();
                if (lane == 0) {
                    unsigned v = (unsigned)(t + 1);
                    asm volatile("st.release.cta.shared.b32 [%0], %1;"
                                 :: "r"(ha), "r"(v) : "memory");
                }
            }
        }

        asm volatile("barrier.cluster.wait.aligned;" ::: "memory");
    } else {
        // ================= WRITER WARP =================
        const int pw = w - CWARPS;
        const uint32_t ha = (uint32_t)__cvta_generic_to_shared(&head[pw]);
        float* gb = out + FR + (size_t)row * NSP + (half * OWN_CTA + pw * OWNW);

        #pragma unroll 1
        for (int t = 0; t < NSTEP; t++) {
            if (t > 0 && (t & (KEX - 1)) == 0) {
                // mirror compute's cluster-barrier cadence
                asm volatile("barrier.cluster.wait.aligned;"   ::: "memory");
                asm volatile("barrier.cluster.arrive.aligned;" ::: "memory");
                asm volatile("barrier.cluster.wait.aligned;"   ::: "memory");
                asm volatile("barrier.cluster.arrive.aligned;" ::: "memory");
            }

            if ((t & 1) == 0) {
                // wait (acquire) until frames t, t+1 are staged
                unsigned v;
                while (true) {
                    asm volatile("ld.acquire.cta.shared.b32 %0, [%1];"
                                 : "=r"(v) : "r"(ha));
                    if (v >= (unsigned)(t + 2)) break;
                    __nanosleep(64);
                }
            }

            // copy frame t+1 (1 KB): coalesced, streaming
            const float4* src = reinterpret_cast<const float4*>(&ring[pw][t & (NBUF - 1)][0]);
            float4* dst = reinterpret_cast<float4*>(gb + (size_t)t * FR);
            float4 a = src[lane];
            float4 b = src[lane + 32];
            __stcs(dst + lane, a);
            __stcs(dst + lane + 32, b);

            if (t & 1) {
                __syncwarp();                         // all lanes' reads consumed
                if (lane == 0) done[pw] = (unsigned)(t + 1);
            }
        }

        asm volatile("barrier.cluster.wait.aligned;" ::: "memory");
    }
}

extern "C" void kernel_launch(void* const* d_in, const int* in_sizes, int n_in,
                              void* d_out, int out_size) {
    const float* u0    = (const float*)d_in[0];
    const float* c     = (const float*)d_in[1];
    const float* alpha = (const float*)d_in[2];
    const float* beta  = (const float*)d_in[3];
    float* out = (float*)d_out;

    ks_kernel<<<BATCH * 2, THREADS>>>(u0, c, alpha, beta, out);
}

// round 8
// speedup vs baseline: 1.3201x; 1.3201x over previous
#include <cuda_runtime.h>
#include <cstdint>

#define NSP     2048
#define BATCH   64
#define NSTEP   1000
#define KEX     32            // steps between ghost exchanges
#define GW      64            // ghost width per side (= 2 * KEX)
#define OWNW    256           // owned elems per warp
#define COVER   384           // OWNW + 2*GW
#define EPT     12            // elems per thread (COVER/32)
#define THREADS 128           // 4 warps per CTA
#define OWN_CTA 1024          // owned per CTA (half row)

typedef unsigned long long u64;

__device__ __forceinline__ u64 pk(float lo, float hi) {
    u64 r; asm("mov.b64 %0,{%1,%2};" : "=l"(r) : "f"(lo), "f"(hi)); return r;
}
__device__ __forceinline__ void upk(u64 v, float& lo, float& hi) {
    asm("mov.b64 {%0,%1},%2;" : "=f"(lo), "=f"(hi) : "l"(v));
}
__device__ __forceinline__ u64 fma2(u64 a, u64 b, u64 c) {
    u64 d; asm("fma.rn.f32x2 %0,%1,%2,%3;" : "=l"(d) : "l"(a), "l"(b), "l"(c)); return d;
}
__device__ __forceinline__ u64 add2(u64 a, u64 b) {
    u64 d; asm("add.rn.f32x2 %0,%1,%2;" : "=l"(d) : "l"(a), "l"(b)); return d;
}
__device__ __forceinline__ u64 mul2(u64 a, u64 b) {
    u64 d; asm("mul.rn.f32x2 %0,%1,%2;" : "=l"(d) : "l"(a), "l"(b)); return d;
}

__global__ void __cluster_dims__(2, 1, 1) __launch_bounds__(THREADS, 1)
ks_kernel(const float* __restrict__ u0,
          const float* __restrict__ cp,
          const float* __restrict__ ap,
          const float* __restrict__ bp,
          float* __restrict__ out) {
    __shared__ alignas(16) float sh_ex[OWN_CTA];          // exchange staging (4 KB)
    __shared__ alignas(16) float ring[4][2][OWNW];        // per-warp 2-frame ring (8 KB)

    const int row  = blockIdx.x >> 1;
    const int half = blockIdx.x & 1;
    const int w    = threadIdx.x >> 5;
    const int lane = threadIdx.x & 31;

    const float dt = 0.01f;
    const float Af = -0.5f * dt * (*cp);
    const float Bc = -dt * (*ap);
    const float Cc = -dt * (*bp);
    const float c0f = 1.0f - 2.0f * Bc + 6.0f * Cc;
    const float c1f = Bc - 4.0f * Cc;
    const u64 C0 = pk(c0f, c0f), C1 = pk(c1f, c1f), C2 = pk(Cc, Cc);
    const u64 AV = pk(Af, Af),   M1 = pk(-1.0f, -1.0f);

    // warp cover: local coord j in [0, COVER); global row pos = base + j (mod NSP)
    const int base = half * OWN_CTA + w * OWNW - GW;    // may be negative
    const int j0   = lane * EPT;

    // ---- initial load: 3 float4 groups per thread, periodic wrap ----
    u64 P[6];
    const float* urow = u0 + (size_t)row * NSP;
    #pragma unroll
    for (int g = 0; g < 3; g++) {
        int pos = (base + j0 + 4 * g) & (NSP - 1);
        float4 v = *reinterpret_cast<const float4*>(urow + pos);
        P[2 * g]     = pk(v.x, v.y);
        P[2 * g + 1] = pk(v.z, v.w);
    }

    // ---- frame 0 = u0 (owned groups only; one-time direct store) ----
    {
        float* o0 = out + (size_t)row * NSP;
        #pragma unroll
        for (int g = 0; g < 3; g++) {
            int j = j0 + 4 * g;
            if (j >= GW && j < GW + OWNW) {
                ulonglong2 v; v.x = P[2 * g]; v.y = P[2 * g + 1];
                *reinterpret_cast<ulonglong2*>(o0 + base + j) = v;
            }
        }
    }

    const uint32_t shbase = (uint32_t)__cvta_generic_to_shared(sh_ex);
    const uint32_t peer   = (uint32_t)(half ^ 1);

    // frame-1 base pointer for this warp's owned 1 KB slice
    const size_t FR = (size_t)BATCH * NSP;
    float* gbase = out + FR + (size_t)row * NSP + (half * OWN_CTA + w * OWNW);

    // initial cluster arrive — pairs with the first exchange's wait
    asm volatile("barrier.cluster.arrive.aligned;" ::: "memory");

    #pragma unroll 1
    for (int t = 0; t < NSTEP; t++) {
        if (t > 0 && (t & (KEX - 1)) == 0) {
            // ===== ghost exchange (every KEX steps) =====
            asm volatile("barrier.cluster.wait.aligned;" ::: "memory");

            // publish my owned 256 elems to sh_ex
            #pragma unroll
            for (int g = 0; g < 3; g++) {
                int j = j0 + 4 * g;
                if (j >= GW && j < GW + OWNW) {
                    float a, b, c, d;
                    upk(P[2 * g], a, b); upk(P[2 * g + 1], c, d);
                    *reinterpret_cast<float4*>(&sh_ex[w * OWNW + (j - GW)]) =
                        make_float4(a, b, c, d);
                }
            }
            __syncthreads();
            asm volatile("barrier.cluster.arrive.aligned;" ::: "memory");
            asm volatile("barrier.cluster.wait.aligned;"   ::: "memory"); // both ready

            // refill ghost groups from own sh_ex or peer sh_ex (DSMEM)
            #pragma unroll
            for (int g = 0; g < 3; g++) {
                int j = j0 + 4 * g;
                if (j < GW || j >= GW + OWNW) {
                    int pos = (base + j) & (NSP - 1);
                    int h2  = pos >> 10;            // owning half
                    int idx = pos & (OWN_CTA - 1);
                    float4 v;
                    if (h2 == half) {
                        v = *reinterpret_cast<const float4*>(&sh_ex[idx]);
                    } else {
                        uint32_t pa;
                        asm("mapa.shared::cluster.u32 %0, %1, %2;"
                            : "=r"(pa) : "r"(shbase + (uint32_t)idx * 4u), "r"(peer));
                        asm volatile("ld.shared::cluster.v4.f32 {%0,%1,%2,%3}, [%4];"
                                     : "=f"(v.x), "=f"(v.y), "=f"(v.z), "=f"(v.w)
                                     : "r"(pa));
                    }
                    P[2 * g]     = pk(v.x, v.y);
                    P[2 * g + 1] = pk(v.z, v.w);
                }
            }
            __syncthreads();
            asm volatile("barrier.cluster.arrive.aligned;" ::: "memory");
        }

        // ===== one explicit-Euler step, fully in registers =====
        float e[16];
        #pragma unroll
        for (int p = 0; p < 6; p++) upk(P[p], e[2 + 2 * p], e[3 + 2 * p]);
        e[0]  = __shfl_up_sync(0xffffffffu, e[12], 1);
        e[1]  = __shfl_up_sync(0xffffffffu, e[13], 1);
        e[14] = __shfl_down_sync(0xffffffffu, e[2], 1);
        e[15] = __shfl_down_sync(0xffffffffu, e[3], 1);

        u64 A[8];
        A[0] = pk(e[0], e[1]);
        #pragma unroll
        for (int p = 0; p < 6; p++) A[p + 1] = P[p];
        A[7] = pk(e[14], e[15]);
        u64 O[7];
        #pragma unroll
        for (int i = 0; i < 7; i++) O[i] = pk(e[2 * i + 1], e[2 * i + 2]);

        u64 r[6];
        #pragma unroll
        for (int p = 0; p < 6; p++) {
            u64 u   = A[p + 1];
            u64 d1  = fma2(M1, O[p], O[p + 1]);     // up1 - um1
            u64 t1  = fma2(AV, d1, C0);             // c0 + A*d1
            u64 s1  = add2(O[p + 1], O[p]);
            u64 s2  = add2(A[p + 2], A[p]);
            u64 m   = mul2(C2, s2);
            m       = fma2(C1, s1, m);
            r[p]    = fma2(u, t1, m);               // u*(c0+A*d1) + C1*s1+C2*s2
        }

        // ---- stage owned groups into this warp's ring slot (conflict-free) ----
        {
            float* sb = &ring[w][t & 1][0];
            #pragma unroll
            for (int g = 0; g < 3; g++) {
                int j = j0 + 4 * g;
                if (j >= GW && j < GW + OWNW) {
                    ulonglong2 v; v.x = r[2 * g]; v.y = r[2 * g + 1];
                    *reinterpret_cast<ulonglong2*>(sb + (j - GW)) = v;
                }
            }
        }
        #pragma unroll
        for (int p = 0; p < 6; p++) P[p] = r[p];

        // ---- every 2 steps: flush both staged frames, fully coalesced ----
        if (t & 1) {
            __syncwarp();    // all lanes' STS for slots 0 and 1 visible warp-wide
            const float4* s0 = reinterpret_cast<const float4*>(&ring[w][0][0]);
            const float4* s1 = reinterpret_cast<const float4*>(&ring[w][1][0]);
            float4* d0 = reinterpret_cast<float4*>(gbase + (size_t)(t - 1) * FR); // frame t
            float4* d1 = reinterpret_cast<float4*>(gbase + (size_t)t * FR);       // frame t+1
            float4 a0 = s0[lane];
            float4 b0 = s0[lane + 32];
            float4 a1 = s1[lane];
            float4 b1 = s1[lane + 32];
            __stcs(d0 + lane,      a0);
            __stcs(d0 + lane + 32, b0);
            __stcs(d1 + lane,      a1);
            __stcs(d1 + lane + 32, b1);
        }
    }

    // pair the final outstanding cluster arrive
    asm volatile("barrier.cluster.wait.aligned;" ::: "memory");
}

extern "C" void kernel_launch(void* const* d_in, const int* in_sizes, int n_in,
                              void* d_out, int out_size) {
    const float* u0    = (const float*)d_in[0];
    const float* c     = (const float*)d_in[1];
    const float* alpha = (const float*)d_in[2];
    const float* beta  = (const float*)d_in[3];
    float* out = (float*)d_out;

    ks_kernel<<<BATCH * 2, THREADS>>>(u0, c, alpha, beta, out);
}

// round 9
// speedup vs baseline: 1.6272x; 1.2327x over previous
#include <cuda_runtime.h>
#include <cstdint>

#define NSP     2048
#define BATCH   64
#define NSTEP   1000
#define KEX     32            // steps between ghost exchanges
#define GW      64            // ghost width per side (= 2 * KEX)
#define OWNW    128           // owned elems per warp
#define COVER   256           // OWNW + 2*GW
#define EPT     8             // elems per thread (COVER/32)
#define THREADS 256           // 8 warps per CTA
#define OWN_CTA 1024          // owned per CTA (half row)

typedef unsigned long long u64;

__device__ __forceinline__ u64 pk(float lo, float hi) {
    u64 r; asm("mov.b64 %0,{%1,%2};" : "=l"(r) : "f"(lo), "f"(hi)); return r;
}
__device__ __forceinline__ void upk(u64 v, float& lo, float& hi) {
    asm("mov.b64 {%0,%1},%2;" : "=f"(lo), "=f"(hi) : "l"(v));
}
__device__ __forceinline__ u64 fma2(u64 a, u64 b, u64 c) {
    u64 d; asm("fma.rn.f32x2 %0,%1,%2,%3;" : "=l"(d) : "l"(a), "l"(b), "l"(c)); return d;
}
__device__ __forceinline__ u64 add2(u64 a, u64 b) {
    u64 d; asm("add.rn.f32x2 %0,%1,%2;" : "=l"(d) : "l"(a), "l"(b)); return d;
}
__device__ __forceinline__ u64 mul2(u64 a, u64 b) {
    u64 d; asm("mul.rn.f32x2 %0,%1,%2;" : "=l"(d) : "l"(a), "l"(b)); return d;
}

__global__ void __cluster_dims__(2, 1, 1) __launch_bounds__(THREADS, 1)
ks_kernel(const float* __restrict__ u0,
          const float* __restrict__ cp,
          const float* __restrict__ ap,
          const float* __restrict__ bp,
          float* __restrict__ out) {
    __shared__ alignas(16) float sh_ex[OWN_CTA];   // exchange staging (4 KB)

    const int row  = blockIdx.x >> 1;
    const int half = blockIdx.x & 1;
    const int w    = threadIdx.x >> 5;
    const int lane = threadIdx.x & 31;

    const float dt = 0.01f;
    const float Af = -0.5f * dt * (*cp);
    const float Bc = -dt * (*ap);
    const float Cc = -dt * (*bp);
    const float c0f = 1.0f - 2.0f * Bc + 6.0f * Cc;
    const float c1f = Bc - 4.0f * Cc;
    const u64 C0 = pk(c0f, c0f), C1 = pk(c1f, c1f), C2 = pk(Cc, Cc);
    const u64 AV = pk(Af, Af),   M1 = pk(-1.0f, -1.0f);

    // warp cover: local coord j in [0, COVER); global row pos = base + j (mod NSP)
    const int base = half * OWN_CTA + w * OWNW - GW;   // may be negative
    const int j0   = lane * EPT;

    // owned region [GW, GW+OWNW) is lane-aligned: lanes 8..23, both groups
    const bool owned = (lane >= 8) && (lane < 24);

    // ---- initial load: 2 float4 groups per thread, periodic wrap ----
    u64 P[4];
    const float* urow = u0 + (size_t)row * NSP;
    #pragma unroll
    for (int g = 0; g < 2; g++) {
        int pos = (base + j0 + 4 * g) & (NSP - 1);
        float4 v = *reinterpret_cast<const float4*>(urow + pos);
        P[2 * g]     = pk(v.x, v.y);
        P[2 * g + 1] = pk(v.z, v.w);
    }

    // ---- frame 0 = u0 (owned lanes: fully coalesced 32 B per lane) ----
    if (owned) {
        ulonglong2* o0 = reinterpret_cast<ulonglong2*>(
            out + (size_t)row * NSP + base + j0);
        ulonglong2 v0; v0.x = P[0]; v0.y = P[1];
        ulonglong2 v1; v1.x = P[2]; v1.y = P[3];
        o0[0] = v0; o0[1] = v1;
    }

    const uint32_t shbase = (uint32_t)__cvta_generic_to_shared(sh_ex);
    const uint32_t peer   = (uint32_t)(half ^ 1);

    const size_t FR = (size_t)BATCH * NSP;
    // per-thread output cursor (used only by owned lanes), frame 1
    float* op = out + FR + (size_t)row * NSP + (base + j0);

    // initial cluster arrive — pairs with the first exchange's wait
    asm volatile("barrier.cluster.arrive.aligned;" ::: "memory");

    #pragma unroll 1
    for (int t = 0; t < NSTEP; t++) {
        if (t > 0 && (t & (KEX - 1)) == 0) {
            // ===== ghost exchange (every KEX steps) =====
            // wait: peer done reading my sh_ex from previous exchange
            asm volatile("barrier.cluster.wait.aligned;" ::: "memory");

            // publish my owned 128 elems into CTA staging [0,1024)
            if (owned) {
                float a, b, c, d;
                float* s = &sh_ex[w * OWNW + (j0 - GW)];
                upk(P[0], a, b); upk(P[1], c, d);
                reinterpret_cast<float4*>(s)[0] = make_float4(a, b, c, d);
                upk(P[2], a, b); upk(P[3], c, d);
                reinterpret_cast<float4*>(s)[1] = make_float4(a, b, c, d);
            }
            __syncthreads();
            asm volatile("barrier.cluster.arrive.aligned;" ::: "memory");
            asm volatile("barrier.cluster.wait.aligned;"   ::: "memory"); // both ready

            // refill ghost lanes from own sh_ex or peer sh_ex (DSMEM)
            if (!owned) {
                #pragma unroll
                for (int g = 0; g < 2; g++) {
                    int pos = (base + j0 + 4 * g) & (NSP - 1);
                    int h2  = pos >> 10;            // owning half
                    int idx = pos & (OWN_CTA - 1);
                    float4 v;
                    if (h2 == half) {
                        v = *reinterpret_cast<const float4*>(&sh_ex[idx]);
                    } else {
                        uint32_t pa;
                        asm("mapa.shared::cluster.u32 %0, %1, %2;"
                            : "=r"(pa) : "r"(shbase + (uint32_t)idx * 4u), "r"(peer));
                        asm volatile("ld.shared::cluster.v4.f32 {%0,%1,%2,%3}, [%4];"
                                     : "=f"(v.x), "=f"(v.y), "=f"(v.z), "=f"(v.w)
                                     : "r"(pa));
                    }
                    P[2 * g]     = pk(v.x, v.y);
                    P[2 * g + 1] = pk(v.z, v.w);
                }
            }
            __syncthreads();
            // arrive: my CTA done reading peer sh_ex
            asm volatile("barrier.cluster.arrive.aligned;" ::: "memory");
        }

        // ===== one explicit-Euler step, registers + 2 u64 shuffles =====
        // neighbor edge pairs are whole P registers: no repacking needed
        u64 prev = __shfl_up_sync(0xffffffffu, P[3], 1);   // lane-1's (e6,e7)
        u64 next = __shfl_down_sync(0xffffffffu, P[0], 1); // lane+1's (e0,e1)

        // aligned pairs A[0..5] covering e[-2..9]
        u64 A[6];
        A[0] = prev; A[1] = P[0]; A[2] = P[1]; A[3] = P[2]; A[4] = P[3]; A[5] = next;

        float a[12];
        #pragma unroll
        for (int i = 0; i < 6; i++) upk(A[i], a[2 * i], a[2 * i + 1]);
        // odd pairs O[i] = (e[2i-1], e[2i]) staggered
        u64 O[5];
        #pragma unroll
        for (int i = 0; i < 5; i++) O[i] = pk(a[2 * i + 1], a[2 * i + 2]);

        u64 r[4];
        #pragma unroll
        for (int p = 0; p < 4; p++) {
            u64 u   = A[p + 1];
            u64 d1  = fma2(M1, O[p], O[p + 1]);     // up1 - um1
            u64 t1  = fma2(AV, d1, C0);             // c0 + A*d1
            u64 s1  = add2(O[p + 1], O[p]);
            u64 s2  = add2(A[p + 2], A[p]);
            u64 m   = mul2(C2, s2);
            m       = fma2(C1, s1, m);
            r[p]    = fma2(u, t1, m);               // u*(c0+A*d1) + C1*s1 + C2*s2
        }

        // trajectory frame t+1: owned lanes, naturally coalesced 32 B/lane
        if (owned) {
            ulonglong2* d = reinterpret_cast<ulonglong2*>(op);
            ulonglong2 v0; v0.x = r[0]; v0.y = r[1];
            ulonglong2 v1; v1.x = r[2]; v1.y = r[3];
            d[0] = v0; d[1] = v1;
        }
        op += FR;

        P[0] = r[0]; P[1] = r[1]; P[2] = r[2]; P[3] = r[3];
    }

    // pair the final outstanding cluster arrive
    asm volatile("barrier.cluster.wait.aligned;" ::: "memory");
}

extern "C" void kernel_launch(void* const* d_in, const int* in_sizes, int n_in,
                              void* d_out, int out_size) {
    const float* u0    = (const float*)d_in[0];
    const float* c     = (const float*)d_in[1];
    const float* alpha = (const float*)d_in[2];
    const float* beta  = (const float*)d_in[3];
    float* out = (float*)d_out;

    ks_kernel<<<BATCH * 2, THREADS>>>(u0, c, alpha, beta, out);
}